// round 7
// baseline (speedup 1.0000x reference)
#include <cuda_runtime.h>

#define NATOMS 4096
#define DDESC  352
#define TILE   32
#define HID    256

// -------- scratch (device globals; no allocation allowed) --------
__device__ float4 g_xyz4[NATOMS];         // {x, y, z, (float)type}  SoA-packed
__device__ float  g_descT[DDESC * 8192];  // transposed: [d][slot]; type0 slots 0.., type1 4096..
__device__ int    g_slot_atom[8192];
__device__ int    g_cnt[2];
__device__ float  g_energy[NATOMS];

// Pack xyz + type into one float4 per atom; also zero the slot counters.
__global__ __launch_bounds__(256) void prep_kernel(
    const float* __restrict__ xyz, const int* __restrict__ types)
{
    int i = blockIdx.x * 256 + threadIdx.x;
    float4 p;
    p.x = xyz[3*i];
    p.y = xyz[3*i+1];
    p.z = xyz[3*i+2];
    p.w = (float)types[i];
    g_xyz4[i] = p;
    if (i < 2) g_cnt[i] = 0;
}

// Packed fp32x2 FMA (Blackwell sm_100+; exact IEEE FMA per 32-bit lane).
__device__ __forceinline__ unsigned long long ffma2(
    unsigned long long a, unsigned long long b, unsigned long long c)
{
    unsigned long long d;
    asm("fma.rn.f32x2 %0, %1, %2, %3;" : "=l"(d) : "l"(a), "l"(b), "l"(c));
    return d;
}
__device__ __forceinline__ unsigned long long pack2(float w) {
    unsigned long long p;
    asm("mov.b64 %0, {%1, %1};" : "=l"(p) : "f"(w));
    return p;
}
__device__ __forceinline__ void unpack2(unsigned long long p, float& lo, float& hi) {
    asm("mov.b64 {%0, %1}, %2;" : "=f"(lo), "=f"(hi) : "l"(p));
}

// Inclusive block scan over 256 threads (3 barriers, shuffle-based).
__device__ __forceinline__ int block_scan_incl(int v, int tid, int* wsum) {
    const int lane = tid & 31, w = tid >> 5;
    #pragma unroll
    for (int off = 1; off < 32; off <<= 1) {
        int u = __shfl_up_sync(0xffffffffu, v, off);
        if (lane >= off) v += u;
    }
    if (lane == 31) wsum[w] = v;
    __syncthreads();
    if (w == 0) {
        int s = (lane < 8) ? wsum[lane] : 0;
        #pragma unroll
        for (int off = 1; off < 8; off <<= 1) {
            int u = __shfl_up_sync(0xffffffffu, s, off);
            if (lane >= off) s += u;
        }
        if (lane < 8) wsum[lane] = s;
    }
    __syncthreads();
    if (w > 0) v += wsum[w - 1];
    __syncthreads();          // wsum free for reuse by next call
    return v;
}

// =====================================================================
// Descriptor kernel: one block (256 thr) per atom.
// One LDG.128 per neighbor (packed xyz+type). Registers hold all 4096
// distances (16/thread). Exact 2-pass radix select of the 128 smallest
// per type, then hybrid register/shared bitonic sort of 256 keys
// (distbits<<32)|idx -> JAX top_k stable order.
// =====================================================================
__global__ __launch_bounds__(256) void desc_kernel(
    const float* __restrict__ box)
{
    const int i   = blockIdx.x;
    const int tid = threadIdx.x;

    __shared__ int hist[4096];
    __shared__ int wsum[8];
    __shared__ unsigned long long bufKey[256];
    __shared__ float s_sd[2][128];
    __shared__ int   s_idx[2][16];
    __shared__ float s_desc[DDESC];
    __shared__ float s_frame[9];
    __shared__ int s_bin, s_before, s_dig, s_count, s_slot;

    const float bx = box[0], by = box[1], bz = box[2];
    const float ibx = 1.0f / bx, iby = 1.0f / by, ibz = 1.0f / bz;
    const float4 pi = g_xyz4[i];
    const float xi = pi.x, yi = pi.y, zi = pi.z;

    // ---- distances for all 4096 atoms, kept in registers ----
    unsigned dbits[16];
    unsigned mask0 = 0, mask1 = 0;
    #pragma unroll
    for (int s = 0; s < 16; s++) {
        int j = s * 256 + tid;
        float4 p = __ldg(&g_xyz4[j]);
        float dx = xi - p.x + 1e-16f;
        float dy = yi - p.y + 1e-16f;
        float dz = zi - p.z + 1e-16f;
        dx -= bx * rintf(dx * ibx);
        dy -= by * rintf(dy * iby);
        dz -= bz * rintf(dz * ibz);
        float d = sqrtf(dx*dx + dy*dy + dz*dz);
        unsigned b = __float_as_uint(d);
        if (j == i) b = 0x7F800000u;          // self -> +inf, excluded anyway
        dbits[s] = b;
        if (j != i) {
            if (p.w == 0.0f) mask0 |= 1u << s;
            else             mask1 |= 1u << s;
        }
    }

    // ---- per-type exact selection of 128 smallest, sorted ----
    for (int t = 0; t < 2; t++) {
        unsigned tm = (t == 0) ? mask0 : mask1;

        // pass 1: 13-bit histogram of float bits [31:19]
        #pragma unroll
        for (int q = 0; q < 16; q++) hist[q*256 + tid] = 0;
        __syncthreads();
        #pragma unroll
        for (int s = 0; s < 16; s++)
            if ((tm >> s) & 1u) atomicAdd(&hist[dbits[s] >> 19], 1);
        __syncthreads();

        // locate rank-128 bin: scan of per-thread 16-bin sums
        int ls = 0;
        const int b0 = tid * 16;
        #pragma unroll
        for (int q = 0; q < 16; q++) ls += hist[b0 + q];
        int v = block_scan_incl(ls, tid, wsum);
        int before = v - ls;
        if (before < 128 && v >= 128) {
            int c = before;
            #pragma unroll
            for (int q = 0; q < 16; q++) {
                int h = hist[b0 + q];
                if (c + h >= 128) { s_bin = b0 + q; s_before = c; break; }
                c += h;
            }
        }
        __syncthreads();
        const int kk     = 128 - s_before;
        const int binsel = s_bin;

        // pass 2: 8-bit refine within selected bin
        hist[tid] = 0;
        __syncthreads();
        #pragma unroll
        for (int s = 0; s < 16; s++)
            if (((tm >> s) & 1u) && (int)(dbits[s] >> 19) == binsel)
                atomicAdd(&hist[(dbits[s] >> 11) & 255], 1);
        __syncthreads();
        int hv = hist[tid];
        int vv = block_scan_incl(hv, tid, wsum);
        int prev = vv - hv;
        if (prev < kk && vv >= kk) s_dig = tid;
        if (tid == 0) s_count = 0;
        __syncthreads();
        const unsigned pivot21 = ((unsigned)binsel << 8) | (unsigned)s_dig;

        // gather candidates with 21-bit prefix <= pivot (~128-132 of them)
        #pragma unroll
        for (int s = 0; s < 16; s++) {
            if (((tm >> s) & 1u) && (dbits[s] >> 11) <= pivot21) {
                int sl = atomicAdd(&s_count, 1);
                if (sl < 256)
                    bufKey[sl] = ((unsigned long long)dbits[s] << 32) |
                                 (unsigned)(s*256 + tid);
            }
        }
        __syncthreads();
        const int n = (s_count < 256) ? s_count : 256;
        unsigned long long key = (tid < n) ? bufKey[tid] : 0xFFFFFFFFFFFFFFFFull;
        __syncthreads();

        // hybrid bitonic sort, 256 keys ascending, one key per thread.
        // j<32  -> shfl exchange (no barriers); j>=32 -> shared roundtrip.
        #pragma unroll
        for (int ksz = 2; ksz <= 256; ksz <<= 1) {
            #pragma unroll
            for (int jst = ksz >> 1; jst > 0; jst >>= 1) {
                const bool up = ((tid & ksz) == 0);
                unsigned long long other;
                if (jst >= 32) {
                    bufKey[tid] = key;
                    __syncthreads();
                    other = bufKey[tid ^ jst];
                    __syncthreads();
                } else {
                    other = __shfl_xor_sync(0xffffffffu, key, jst);
                }
                const bool keep_min = (((tid & jst) == 0) == up);
                const bool swap = keep_min ? (other < key) : (other > key);
                if (swap) key = other;
            }
        }
        if (tid < 128) {
            s_sd[t][tid] = __uint_as_float((unsigned)(key >> 32));
            if (tid < 16) s_idx[t][tid] = (int)(key & 0xFFFFFFFFu);
        }
        __syncthreads();
    }

    // ---- inverse-distance descriptor blocks ----
    {
        int t = tid >> 7, r = tid & 127;
        s_desc[tid] = 1.0f / (s_sd[t][r] + 1e-16f);
    }

    // ---- local frame (thread 0; trivial) ----
    if (tid == 0) {
        float cd[4]; int ci[4];
        cd[0]=s_sd[0][0]; ci[0]=s_idx[0][0];
        cd[1]=s_sd[0][1]; ci[1]=s_idx[0][1];
        cd[2]=s_sd[1][0]; ci[2]=s_idx[1][0];
        cd[3]=s_sd[1][1]; ci[3]=s_idx[1][1];
        int a0 = 0;
        for (int q = 1; q < 4; q++) if (cd[q] < cd[a0]) a0 = q;   // stable min
        int a1 = -1;
        for (int q = 0; q < 4; q++) if (q != a0 && (a1 < 0 || cd[q] < cd[a1])) a1 = q;

        float r0[3], r1[3];
        for (int p = 0; p < 2; p++) {
            int sel = p ? a1 : a0;
            float4 pj = g_xyz4[ci[sel]];
            float dm0 = xi - pj.x + 1e-16f;
            float dm1 = yi - pj.y + 1e-16f;
            float dm2 = zi - pj.z + 1e-16f;
            dm0 -= bx * rintf(dm0 * ibx);
            dm1 -= by * rintf(dm1 * iby);
            dm2 -= bz * rintf(dm2 * ibz);
            float den = cd[sel] + 1e-16f;
            float* r = p ? r1 : r0;
            r[0] = dm0/den; r[1] = dm1/den; r[2] = dm2/den;
        }
        float dot = r0[0]*r1[0] + r0[1]*r1[1] + r0[2]*r1[2];
        float v2[3] = { r1[0]-dot*r0[0], r1[1]-dot*r0[1], r1[2]-dot*r0[2] };
        float n2 = sqrtf(v2[0]*v2[0] + v2[1]*v2[1] + v2[2]*v2[2]);
        v2[0] /= n2; v2[1] /= n2; v2[2] /= n2;
        float v3[3] = { r0[1]*r1[2]-r0[2]*r1[1],
                        r0[2]*r1[0]-r0[0]*r1[2],
                        r0[0]*r1[1]-r0[1]*r1[0] };
        float n3 = sqrtf(v3[0]*v3[0] + v3[1]*v3[1] + v3[2]*v3[2]);
        v3[0] /= n3; v3[1] /= n3; v3[2] /= n3;
        s_frame[0]=r0[0]; s_frame[1]=r0[1]; s_frame[2]=r0[2];
        s_frame[3]=v2[0]; s_frame[4]=v2[1]; s_frame[5]=v2[2];
        s_frame[6]=v3[0]; s_frame[7]=v3[1]; s_frame[8]=v3[2];

        int ti = (pi.w != 0.0f) ? 1 : 0;
        int sl = 4096*ti + atomicAdd(&g_cnt[ti], 1);
        g_slot_atom[sl] = i;
        s_slot = sl;
    }
    __syncthreads();

    // ---- rotated angular part: 32 neighbors x 3 components ----
    if (tid < 32) {
        int t = tid >> 4, r = tid & 15;
        float4 pj = g_xyz4[s_idx[t][r]];
        float d = s_sd[t][r];
        float dm0 = xi - pj.x + 1e-16f;
        float dm1 = yi - pj.y + 1e-16f;
        float dm2 = zi - pj.z + 1e-16f;
        dm0 -= bx * rintf(dm0 * ibx);
        dm1 -= by * rintf(dm1 * iby);
        dm2 -= bz * rintf(dm2 * ibz);
        float den = d + 1e-16f;
        float anx = dm0/den, any = dm1/den, anz = dm2/den;
        #pragma unroll
        for (int rr = 0; rr < 3; rr++) {
            float val = s_frame[3*rr+0]*anx + s_frame[3*rr+1]*any + s_frame[3*rr+2]*anz;
            s_desc[256 + 3*tid + rr] = val / den;
        }
    }
    __syncthreads();

    const int sl = s_slot;
    for (int c = tid; c < DDESC; c += 256)
        g_descT[c * 8192 + sl] = s_desc[c];
}

// =====================================================================
// MLP kernel: grid (128, 2); 256 threads = one output neuron each,
// TILE=32 atoms per block. Single 45 KB shared buffer. Inner loop uses
// packed fma.rn.f32x2 (FFMA2) + LDS.128 so FMA issue is halved.
// =====================================================================
__device__ __forceinline__ void mlp_layer(
    const float* __restrict__ W, float bb, int din,
    float* __restrict__ sA, int tid)
{
    unsigned long long acc2[TILE/2];
    #pragma unroll
    for (int k = 0; k < TILE/2; k++) acc2[k] = 0ull;   // two packed +0.0f

    #pragma unroll 4
    for (int d = 0; d < din; d++) {
        const unsigned long long w2 = pack2(__ldg(&W[d*HID]));
        const ulonglong2* r2 = (const ulonglong2*)(sA + d*TILE);
        #pragma unroll
        for (int q = 0; q < TILE/4; q++) {
            ulonglong2 r = r2[q];                      // LDS.128 broadcast
            acc2[2*q+0] = ffma2(w2, r.x, acc2[2*q+0]);
            acc2[2*q+1] = ffma2(w2, r.y, acc2[2*q+1]);
        }
    }
    __syncthreads();                  // all reads of sA complete
    float4* out4 = (float4*)(sA + tid*TILE);
    #pragma unroll
    for (int q = 0; q < TILE/4; q++) {
        float a0, a1, a2, a3;
        unpack2(acc2[2*q+0], a0, a1);
        unpack2(acc2[2*q+1], a2, a3);
        float4 o;
        o.x = tanhf(a0 + bb);
        o.y = tanhf(a1 + bb);
        o.z = tanhf(a2 + bb);
        o.w = tanhf(a3 + bb);
        out4[q] = o;
    }
    __syncthreads();
}

__global__ __launch_bounds__(256) void mlp_kernel(
    const float* __restrict__ w1, const float* __restrict__ b1,
    const float* __restrict__ w2, const float* __restrict__ b2,
    const float* __restrict__ w3, const float* __restrict__ b3,
    const float* __restrict__ w4, const float* __restrict__ b4)
{
    __shared__ float sA[DDESC * TILE];        // 45056 B
    __shared__ float s_red[8 * TILE];

    const int t    = blockIdx.y;
    const int cnt  = g_cnt[t];
    const int base = blockIdx.x * TILE;
    if (base >= cnt) return;
    const int slot0 = 4096*t + base;
    const int tid   = threadIdx.x;

    for (int e = tid; e < DDESC*TILE; e += 256) {
        int d = e >> 5, a = e & 31;
        sA[e] = g_descT[d*8192 + slot0 + a];
    }
    __syncthreads();

    mlp_layer(w1 + t*DDESC*HID + tid, b1[t*HID + tid], DDESC, sA, tid);
    mlp_layer(w2 + t*HID*HID  + tid, b2[t*HID + tid], HID,   sA, tid);
    mlp_layer(w3 + t*HID*HID  + tid, b3[t*HID + tid], HID,   sA, tid);

    // ---- layer 4: 256 -> 1, block reduction per atom ----
    {
        float w4v = w4[t*HID + tid];
        float pv[TILE];
        #pragma unroll
        for (int a = 0; a < TILE; a++) pv[a] = w4v * sA[tid*TILE + a];
        #pragma unroll
        for (int off = 16; off; off >>= 1) {
            #pragma unroll
            for (int a = 0; a < TILE; a++)
                pv[a] += __shfl_down_sync(0xffffffffu, pv[a], off);
        }
        if ((tid & 31) == 0) {
            #pragma unroll
            for (int a = 0; a < TILE; a++) s_red[(tid >> 5)*TILE + a] = pv[a];
        }
        __syncthreads();
        if (tid < TILE) {
            float s = 0.f;
            #pragma unroll
            for (int w = 0; w < 8; w++) s += s_red[w*TILE + tid];
            if (base + tid < cnt)
                g_energy[g_slot_atom[slot0 + tid]] = s + b4[t];
        }
    }
}

// =====================================================================
// Deterministic fixed-order final reduction
// =====================================================================
__global__ void reduce_kernel(float* __restrict__ out) {
    __shared__ float sh[1024];
    int tid = threadIdx.x;
    float s = g_energy[tid] + g_energy[tid+1024] +
              g_energy[tid+2048] + g_energy[tid+3072];
    sh[tid] = s;
    __syncthreads();
    for (int off = 512; off; off >>= 1) {
        if (tid < off) sh[tid] += sh[tid + off];
        __syncthreads();
    }
    if (tid == 0) out[0] = sh[0];
}

// =====================================================================
extern "C" void kernel_launch(void* const* d_in, const int* in_sizes, int n_in,
                              void* d_out, int out_size)
{
    const float* xyz   = (const float*)d_in[0];
    const float* box   = (const float*)d_in[1];
    const int*   types = (const int*)d_in[2];
    const float* w1 = (const float*)d_in[3];
    const float* b1 = (const float*)d_in[4];
    const float* w2 = (const float*)d_in[5];
    const float* b2 = (const float*)d_in[6];
    const float* w3 = (const float*)d_in[7];
    const float* b3 = (const float*)d_in[8];
    const float* w4 = (const float*)d_in[9];
    const float* b4 = (const float*)d_in[10];

    prep_kernel<<<NATOMS/256, 256>>>(xyz, types);
    desc_kernel<<<NATOMS, 256>>>(box);
    mlp_kernel<<<dim3(128, 2), 256>>>(w1, b1, w2, b2, w3, b3, w4, b4);
    reduce_kernel<<<1, 1024>>>((float*)d_out);
}

// round 8
// speedup vs baseline: 1.3540x; 1.3540x over previous
#include <cuda_runtime.h>

#define NATOMS 4096
#define DDESC  352
#define TILE   32
#define HID    256
#define NTILES 256          // 8192 slots / 32

// -------- scratch (device globals; no allocation allowed) --------
__device__ float4 g_xyz4[NATOMS];         // {x, y, z, (float)type}
__device__ float  g_descT[DDESC * 8192];  // transposed: [d][slot]; type0 slots 0.., type1 4096..
__device__ int    g_slot_atom[8192];
__device__ int    g_cnt[2];
__device__ int    g_work;
__device__ float  g_energy[NATOMS];

// Pack xyz + type into one float4 per atom; zero counters.
__global__ __launch_bounds__(256) void prep_kernel(
    const float* __restrict__ xyz, const int* __restrict__ types)
{
    int i = blockIdx.x * 256 + threadIdx.x;
    float4 p;
    p.x = xyz[3*i];
    p.y = xyz[3*i+1];
    p.z = xyz[3*i+2];
    p.w = (float)types[i];
    g_xyz4[i] = p;
    if (i < 2) g_cnt[i] = 0;
    if (i == 0) g_work = 0;
}

// Packed fp32x2 FMA (Blackwell; exact IEEE FMA per 32-bit lane).
__device__ __forceinline__ unsigned long long ffma2(
    unsigned long long a, unsigned long long b, unsigned long long c)
{
    unsigned long long d;
    asm("fma.rn.f32x2 %0, %1, %2, %3;" : "=l"(d) : "l"(a), "l"(b), "l"(c));
    return d;
}
__device__ __forceinline__ unsigned long long pack2(float w) {
    unsigned long long p;
    asm("mov.b64 %0, {%1, %1};" : "=l"(p) : "f"(w));
    return p;
}
__device__ __forceinline__ void unpack2(unsigned long long p, float& lo, float& hi) {
    asm("mov.b64 {%0, %1}, %2;" : "=f"(lo), "=f"(hi) : "l"(p));
}

// Inclusive block scan over 256 threads (shuffle-based). Works on packed
// 16+16-bit nonneg counts (each half < 32768 -> no cross-half carry).
__device__ __forceinline__ int block_scan_incl(int v, int tid, int* wsum) {
    const int lane = tid & 31, w = tid >> 5;
    #pragma unroll
    for (int off = 1; off < 32; off <<= 1) {
        int u = __shfl_up_sync(0xffffffffu, v, off);
        if (lane >= off) v += u;
    }
    if (lane == 31) wsum[w] = v;
    __syncthreads();
    if (w == 0) {
        int s = (lane < 8) ? wsum[lane] : 0;
        #pragma unroll
        for (int off = 1; off < 8; off <<= 1) {
            int u = __shfl_up_sync(0xffffffffu, s, off);
            if (lane >= off) s += u;
        }
        if (lane < 8) wsum[lane] = s;
    }
    __syncthreads();
    if (w > 0) v += wsum[w - 1];
    __syncthreads();
    return v;
}

// Hybrid bitonic sort of 256 u64 keys ascending, one per thread.
// jst<32 via shfl (no barriers); jst>=32 via shared roundtrip.
__device__ __forceinline__ unsigned long long sort256(
    unsigned long long key, unsigned long long* buf, int tid)
{
    #pragma unroll
    for (int ksz = 2; ksz <= 256; ksz <<= 1) {
        #pragma unroll
        for (int jst = ksz >> 1; jst > 0; jst >>= 1) {
            const bool up = ((tid & ksz) == 0);
            unsigned long long other;
            if (jst >= 32) {
                buf[tid] = key;
                __syncthreads();
                other = buf[tid ^ jst];
                __syncthreads();
            } else {
                other = __shfl_xor_sync(0xffffffffu, key, jst);
            }
            const bool keep_min = (((tid & jst) == 0) == up);
            const bool swap = keep_min ? (other < key) : (other > key);
            if (swap) key = other;
        }
    }
    return key;
}

// =====================================================================
// Descriptor kernel: one block (256 thr) per atom. Fused dual-type
// radix select (packed 16+16 scans), then two 256-key bitonic sorts
// on (distbits<<32)|idx -> JAX top_k stable order.
// =====================================================================
__global__ __launch_bounds__(256) void desc_kernel(
    const float* __restrict__ box)
{
    const int i   = blockIdx.x;
    const int tid = threadIdx.x;

    __shared__ int hist[8192];                // hist0 | hist1 (32 KB)
    __shared__ int refine[512];               // r0 | r1
    __shared__ int wsum[8];
    __shared__ unsigned long long buf0[256];
    __shared__ unsigned long long buf1[256];
    __shared__ float s_sd[2][128];
    __shared__ int   s_idx[2][16];
    __shared__ float s_desc[DDESC];
    __shared__ float s_frame[9];
    __shared__ int s_bin[2], s_before[2], s_dig[2], s_count[2], s_slot;

    const float bx = box[0], by = box[1], bz = box[2];
    const float ibx = 1.0f / bx, iby = 1.0f / by, ibz = 1.0f / bz;
    const float4 pi = g_xyz4[i];
    const float xi = pi.x, yi = pi.y, zi = pi.z;

    // ---- distances for all 4096 atoms, kept in registers ----
    unsigned dbits[16];
    unsigned mask0 = 0, mask1 = 0;
    #pragma unroll
    for (int s = 0; s < 16; s++) {
        int j = s * 256 + tid;
        float4 p = __ldg(&g_xyz4[j]);
        float dx = xi - p.x + 1e-16f;
        float dy = yi - p.y + 1e-16f;
        float dz = zi - p.z + 1e-16f;
        dx -= bx * rintf(dx * ibx);
        dy -= by * rintf(dy * iby);
        dz -= bz * rintf(dz * ibz);
        float d = sqrtf(dx*dx + dy*dy + dz*dz);
        unsigned b = __float_as_uint(d);
        if (j == i) b = 0x7F800000u;
        dbits[s] = b;
        if (j != i) {
            if (p.w == 0.0f) mask0 |= 1u << s;
            else             mask1 |= 1u << s;
        }
    }

    // ---- zero both histograms (int4) ----
    {
        int4 z = make_int4(0, 0, 0, 0);
        int4* h4 = (int4*)hist;
        #pragma unroll
        for (int k = 0; k < 8; k++) h4[k*256 + tid] = z;
    }
    if (tid < 2) s_count[tid] = 0;
    __syncthreads();

    // ---- one atomic fill pass into both hists ----
    #pragma unroll
    for (int s = 0; s < 16; s++) {
        if ((mask0 >> s) & 1u)      atomicAdd(&hist[dbits[s] >> 19], 1);
        else if ((mask1 >> s) & 1u) atomicAdd(&hist[4096 + (dbits[s] >> 19)], 1);
    }
    __syncthreads();

    // ---- locate rank-128 bin for both types with ONE packed scan ----
    int ls0 = 0, ls1 = 0;
    const int b0 = tid * 16;
    #pragma unroll
    for (int q = 0; q < 16; q++) { ls0 += hist[b0 + q]; ls1 += hist[4096 + b0 + q]; }
    {
        int v = block_scan_incl(ls0 | (ls1 << 16), tid, wsum);
        int v0 = v & 0xffff, v1 = (v >> 16) & 0xffff;
        int before0 = v0 - ls0, before1 = v1 - ls1;
        if (before0 < 128 && v0 >= 128) {
            int c = before0;
            #pragma unroll
            for (int q = 0; q < 16; q++) {
                int h = hist[b0 + q];
                if (c + h >= 128) { s_bin[0] = b0 + q; s_before[0] = c; break; }
                c += h;
            }
        }
        if (before1 < 128 && v1 >= 128) {
            int c = before1;
            #pragma unroll
            for (int q = 0; q < 16; q++) {
                int h = hist[4096 + b0 + q];
                if (c + h >= 128) { s_bin[1] = b0 + q; s_before[1] = c; break; }
                c += h;
            }
        }
    }
    refine[tid] = 0; refine[256 + tid] = 0;
    __syncthreads();
    const int bin0 = s_bin[0], bin1 = s_bin[1];
    const int kk0 = 128 - s_before[0], kk1 = 128 - s_before[1];

    // ---- one refine fill pass (8-bit digit within selected bins) ----
    #pragma unroll
    for (int s = 0; s < 16; s++) {
        if (((mask0 >> s) & 1u) && (int)(dbits[s] >> 19) == bin0)
            atomicAdd(&refine[(dbits[s] >> 11) & 255], 1);
        else if (((mask1 >> s) & 1u) && (int)(dbits[s] >> 19) == bin1)
            atomicAdd(&refine[256 + ((dbits[s] >> 11) & 255)], 1);
    }
    __syncthreads();
    {
        int r0 = refine[tid], r1 = refine[256 + tid];
        int v = block_scan_incl(r0 | (r1 << 16), tid, wsum);
        int v0 = v & 0xffff, v1 = (v >> 16) & 0xffff;
        if (v0 - r0 < kk0 && v0 >= kk0) s_dig[0] = tid;
        if (v1 - r1 < kk1 && v1 >= kk1) s_dig[1] = tid;
    }
    __syncthreads();
    const unsigned pivot0 = ((unsigned)bin0 << 8) | (unsigned)s_dig[0];
    const unsigned pivot1 = ((unsigned)bin1 << 8) | (unsigned)s_dig[1];

    // ---- one gather pass into both candidate buffers ----
    #pragma unroll
    for (int s = 0; s < 16; s++) {
        unsigned pre = dbits[s] >> 11;
        if (((mask0 >> s) & 1u) && pre <= pivot0) {
            int sl = atomicAdd(&s_count[0], 1);
            if (sl < 256)
                buf0[sl] = ((unsigned long long)dbits[s] << 32) | (unsigned)(s*256 + tid);
        } else if (((mask1 >> s) & 1u) && pre <= pivot1) {
            int sl = atomicAdd(&s_count[1], 1);
            if (sl < 256)
                buf1[sl] = ((unsigned long long)dbits[s] << 32) | (unsigned)(s*256 + tid);
        }
    }
    __syncthreads();
    const int n0 = (s_count[0] < 256) ? s_count[0] : 256;
    const int n1 = (s_count[1] < 256) ? s_count[1] : 256;
    unsigned long long k0 = (tid < n0) ? buf0[tid] : 0xFFFFFFFFFFFFFFFFull;
    unsigned long long k1 = (tid < n1) ? buf1[tid] : 0xFFFFFFFFFFFFFFFFull;
    __syncthreads();

    // ---- two sequential 256-key sorts ----
    k0 = sort256(k0, buf0, tid);
    if (tid < 128) {
        s_sd[0][tid] = __uint_as_float((unsigned)(k0 >> 32));
        if (tid < 16) s_idx[0][tid] = (int)(k0 & 0xFFFFFFFFu);
    }
    k1 = sort256(k1, buf1, tid);
    if (tid < 128) {
        s_sd[1][tid] = __uint_as_float((unsigned)(k1 >> 32));
        if (tid < 16) s_idx[1][tid] = (int)(k1 & 0xFFFFFFFFu);
    }
    __syncthreads();

    // ---- inverse-distance descriptor blocks ----
    {
        int t = tid >> 7, r = tid & 127;
        s_desc[tid] = 1.0f / (s_sd[t][r] + 1e-16f);
    }

    // ---- local frame (thread 0; trivial) ----
    if (tid == 0) {
        float cd[4]; int ci[4];
        cd[0]=s_sd[0][0]; ci[0]=s_idx[0][0];
        cd[1]=s_sd[0][1]; ci[1]=s_idx[0][1];
        cd[2]=s_sd[1][0]; ci[2]=s_idx[1][0];
        cd[3]=s_sd[1][1]; ci[3]=s_idx[1][1];
        int a0 = 0;
        for (int q = 1; q < 4; q++) if (cd[q] < cd[a0]) a0 = q;   // stable min
        int a1 = -1;
        for (int q = 0; q < 4; q++) if (q != a0 && (a1 < 0 || cd[q] < cd[a1])) a1 = q;

        float r0[3], r1[3];
        for (int p = 0; p < 2; p++) {
            int sel = p ? a1 : a0;
            float4 pj = g_xyz4[ci[sel]];
            float dm0 = xi - pj.x + 1e-16f;
            float dm1 = yi - pj.y + 1e-16f;
            float dm2 = zi - pj.z + 1e-16f;
            dm0 -= bx * rintf(dm0 * ibx);
            dm1 -= by * rintf(dm1 * iby);
            dm2 -= bz * rintf(dm2 * ibz);
            float den = cd[sel] + 1e-16f;
            float* r = p ? r1 : r0;
            r[0] = dm0/den; r[1] = dm1/den; r[2] = dm2/den;
        }
        float dot = r0[0]*r1[0] + r0[1]*r1[1] + r0[2]*r1[2];
        float v2[3] = { r1[0]-dot*r0[0], r1[1]-dot*r0[1], r1[2]-dot*r0[2] };
        float n2 = sqrtf(v2[0]*v2[0] + v2[1]*v2[1] + v2[2]*v2[2]);
        v2[0] /= n2; v2[1] /= n2; v2[2] /= n2;
        float v3[3] = { r0[1]*r1[2]-r0[2]*r1[1],
                        r0[2]*r1[0]-r0[0]*r1[2],
                        r0[0]*r1[1]-r0[1]*r1[0] };
        float n3 = sqrtf(v3[0]*v3[0] + v3[1]*v3[1] + v3[2]*v3[2]);
        v3[0] /= n3; v3[1] /= n3; v3[2] /= n3;
        s_frame[0]=r0[0]; s_frame[1]=r0[1]; s_frame[2]=r0[2];
        s_frame[3]=v2[0]; s_frame[4]=v2[1]; s_frame[5]=v2[2];
        s_frame[6]=v3[0]; s_frame[7]=v3[1]; s_frame[8]=v3[2];

        int ti = (pi.w != 0.0f) ? 1 : 0;
        int sl = 4096*ti + atomicAdd(&g_cnt[ti], 1);
        g_slot_atom[sl] = i;
        s_slot = sl;
    }
    __syncthreads();

    // ---- rotated angular part: 32 neighbors x 3 components ----
    if (tid < 32) {
        int t = tid >> 4, r = tid & 15;
        float4 pj = g_xyz4[s_idx[t][r]];
        float d = s_sd[t][r];
        float dm0 = xi - pj.x + 1e-16f;
        float dm1 = yi - pj.y + 1e-16f;
        float dm2 = zi - pj.z + 1e-16f;
        dm0 -= bx * rintf(dm0 * ibx);
        dm1 -= by * rintf(dm1 * iby);
        dm2 -= bz * rintf(dm2 * ibz);
        float den = d + 1e-16f;
        float anx = dm0/den, any = dm1/den, anz = dm2/den;
        #pragma unroll
        for (int rr = 0; rr < 3; rr++) {
            float val = s_frame[3*rr+0]*anx + s_frame[3*rr+1]*any + s_frame[3*rr+2]*anz;
            s_desc[256 + 3*tid + rr] = val / den;
        }
    }
    __syncthreads();

    const int sl = s_slot;
    for (int c = tid; c < DDESC; c += 256)
        g_descT[c * 8192 + sl] = s_desc[c];
}

// =====================================================================
// MLP kernel: persistent work-stealing. 296 blocks (2/SM) pull 32-atom
// tiles from a global counter -> perfect SM balance. FFMA2 + LDS.128.
// =====================================================================
__device__ __forceinline__ void mlp_layer(
    const float* __restrict__ W, float bb, int din,
    float* __restrict__ sA, int tid)
{
    unsigned long long acc2[TILE/2];
    #pragma unroll
    for (int k = 0; k < TILE/2; k++) acc2[k] = 0ull;

    #pragma unroll 4
    for (int d = 0; d < din; d++) {
        const unsigned long long w2 = pack2(__ldg(&W[d*HID]));
        const ulonglong2* r2 = (const ulonglong2*)(sA + d*TILE);
        #pragma unroll
        for (int q = 0; q < TILE/4; q++) {
            ulonglong2 r = r2[q];                      // LDS.128 broadcast
            acc2[2*q+0] = ffma2(w2, r.x, acc2[2*q+0]);
            acc2[2*q+1] = ffma2(w2, r.y, acc2[2*q+1]);
        }
    }
    __syncthreads();
    float4* out4 = (float4*)(sA + tid*TILE);
    #pragma unroll
    for (int q = 0; q < TILE/4; q++) {
        float a0, a1, a2, a3;
        unpack2(acc2[2*q+0], a0, a1);
        unpack2(acc2[2*q+1], a2, a3);
        float4 o;
        o.x = tanhf(a0 + bb);
        o.y = tanhf(a1 + bb);
        o.z = tanhf(a2 + bb);
        o.w = tanhf(a3 + bb);
        out4[q] = o;
    }
    __syncthreads();
}

__global__ __launch_bounds__(256) void mlp_kernel(
    const float* __restrict__ w1, const float* __restrict__ b1,
    const float* __restrict__ w2, const float* __restrict__ b2,
    const float* __restrict__ w3, const float* __restrict__ b3,
    const float* __restrict__ w4, const float* __restrict__ b4)
{
    __shared__ float sA[DDESC * TILE];        // 45056 B
    __shared__ float s_red[8 * TILE];
    __shared__ int s_tile;

    const int tid = threadIdx.x;

    for (;;) {
        if (tid == 0) s_tile = atomicAdd(&g_work, 1);
        __syncthreads();
        const int tile = s_tile;
        if (tile >= NTILES) break;            // uniform exit

        const int t    = tile >> 7;
        const int base = (tile & 127) * TILE;
        const int cnt  = g_cnt[t];
        if (base < cnt) {                     // block-uniform condition
            const int slot0 = 4096*t + base;

            for (int e = tid; e < DDESC*TILE; e += 256) {
                int d = e >> 5, a = e & 31;
                sA[e] = g_descT[d*8192 + slot0 + a];
            }
            __syncthreads();

            mlp_layer(w1 + t*DDESC*HID + tid, b1[t*HID + tid], DDESC, sA, tid);
            mlp_layer(w2 + t*HID*HID  + tid, b2[t*HID + tid], HID,   sA, tid);
            mlp_layer(w3 + t*HID*HID  + tid, b3[t*HID + tid], HID,   sA, tid);

            // layer 4: 256 -> 1, block reduction per atom
            float w4v = w4[t*HID + tid];
            float pv[TILE];
            #pragma unroll
            for (int a = 0; a < TILE; a++) pv[a] = w4v * sA[tid*TILE + a];
            #pragma unroll
            for (int off = 16; off; off >>= 1) {
                #pragma unroll
                for (int a = 0; a < TILE; a++)
                    pv[a] += __shfl_down_sync(0xffffffffu, pv[a], off);
            }
            if ((tid & 31) == 0) {
                #pragma unroll
                for (int a = 0; a < TILE; a++) s_red[(tid >> 5)*TILE + a] = pv[a];
            }
            __syncthreads();
            if (tid < TILE) {
                float s = 0.f;
                #pragma unroll
                for (int w = 0; w < 8; w++) s += s_red[w*TILE + tid];
                if (base + tid < cnt)
                    g_energy[g_slot_atom[slot0 + tid]] = s + b4[t];
            }
        }
        __syncthreads();                      // s_tile safe to overwrite
    }
}

// =====================================================================
// Deterministic fixed-order final reduction
// =====================================================================
__global__ void reduce_kernel(float* __restrict__ out) {
    __shared__ float sh[1024];
    int tid = threadIdx.x;
    float s = g_energy[tid] + g_energy[tid+1024] +
              g_energy[tid+2048] + g_energy[tid+3072];
    sh[tid] = s;
    __syncthreads();
    for (int off = 512; off; off >>= 1) {
        if (tid < off) sh[tid] += sh[tid + off];
        __syncthreads();
    }
    if (tid == 0) out[0] = sh[0];
}

// =====================================================================
extern "C" void kernel_launch(void* const* d_in, const int* in_sizes, int n_in,
                              void* d_out, int out_size)
{
    const float* xyz   = (const float*)d_in[0];
    const float* box   = (const float*)d_in[1];
    const int*   types = (const int*)d_in[2];
    const float* w1 = (const float*)d_in[3];
    const float* b1 = (const float*)d_in[4];
    const float* w2 = (const float*)d_in[5];
    const float* b2 = (const float*)d_in[6];
    const float* w3 = (const float*)d_in[7];
    const float* b3 = (const float*)d_in[8];
    const float* w4 = (const float*)d_in[9];
    const float* b4 = (const float*)d_in[10];

    prep_kernel<<<NATOMS/256, 256>>>(xyz, types);
    desc_kernel<<<NATOMS, 256>>>(box);
    mlp_kernel<<<296, 256>>>(w1, b1, w2, b2, w3, b3, w4, b4);
    reduce_kernel<<<1, 1024>>>((float*)d_out);
}